// round 7
// baseline (speedup 1.0000x reference)
#include <cuda_runtime.h>
#include <math.h>

#define N_NODES 8192
#define N_EDGES 4096
#define NNZ_IN  65536
#define DIN_    256
#define D_      128
#define MAXDEG  512

#define EM1     1.7182818284590452f
#define INV_TEMP (1.0f/11.313708498984761f)  // 1/sqrt(128)

typedef unsigned long long ull;

// ---------------- scratch ----------------
__device__ unsigned int g_bitmap[(size_t)N_NODES * N_EDGES / 32];  // 4 MB
__device__ int   g_kept_n[NNZ_IN];
__device__ int   g_kept_e[NNZ_IN];
__device__ int   g_kept_count;
__device__ int   g_deg_e[N_EDGES];
__device__ int   g_deg_n[N_NODES];
__device__ int   g_rowptr_e[N_EDGES + 1];
__device__ int   g_rowptr_n[N_NODES + 1];
__device__ int   g_cur_e[N_EDGES];
__device__ int   g_cur_n[N_NODES];
__device__ int   g_csr_e[NNZ_IN];
__device__ int   g_csr_n[NNZ_IN];
__device__ float4 g_Wpack[(size_t)DIN_ * D_];   // (W,W,W2,W2) broadcast-packed
__device__ float g_x4[(size_t)N_NODES * D_];
__device__ float g_xt[(size_t)N_NODES * D_];
__device__ float g_rowv[N_NODES];
__device__ float g_edge[(size_t)N_EDGES * D_];
__device__ float g_edge4[(size_t)N_EDGES * D_];
__device__ float g_Y[(size_t)N_EDGES * D_];
__device__ float g_Y2[(size_t)N_EDGES * D_];
__device__ float g_Pval[NNZ_IN];
__device__ float g_Qval[NNZ_IN];
__device__ float g_score[NNZ_IN];
__device__ float g_v[N_NODES];
__device__ float g_w[N_NODES];
__device__ float g_r[N_NODES];
__device__ float g_s[D_], g_cxt[D_], g_t[D_], g_p1[D_], g_p2[D_];
__device__ float g_alpha;

// ---------------- f32x2 helpers ----------------
__device__ __forceinline__ void ffma2(ull &acc, ull a, ull b) {
    asm("fma.rn.f32x2 %0, %1, %2, %0;" : "+l"(acc) : "l"(a), "l"(b));
}
__device__ __forceinline__ ull pack2(float v) {
    ull r;
    asm("mov.b64 %0, {%1, %1};" : "=l"(r) : "f"(v));
    return r;
}
__device__ __forceinline__ void unpack2(ull a, float &lo, float &hi) {
    asm("mov.b64 {%0, %1}, %2;" : "=f"(lo), "=f"(hi) : "l"(a));
}

// ---------------- kernels ----------------

// tiny: zero the 128-wide accumulators + alpha (main stream, 1 block)
__global__ void k_zero_small() {
    int i = threadIdx.x;
    if (i < D_) { g_s[i]=0.f; g_cxt[i]=0.f; g_t[i]=0.f; g_p1[i]=0.f; g_p2[i]=0.f; }
    if (i == 0) g_alpha = 0.f;
}

// big: bitmap + per-row counters + v (side stream)
__global__ void k_zero_big() {
    int i = blockIdx.x * blockDim.x + threadIdx.x;
    int stride = gridDim.x * blockDim.x;
    uint4 z4 = make_uint4(0,0,0,0);
    uint4* bm = (uint4*)g_bitmap;
    for (int j = i; j < (int)(sizeof(g_bitmap)/16); j += stride) bm[j] = z4;
    for (int j = i; j < N_EDGES; j += stride) { g_deg_e[j] = 0; g_cur_e[j] = 0; }
    for (int j = i; j < N_NODES; j += stride) { g_deg_n[j] = 0; g_cur_n[j] = 0; g_v[j] = 0.f; }
    if (i == 0) g_kept_count = 0;
}

// pack weights for single-LDG.128 inner loop
__global__ void k_pack(const float* __restrict__ W, const float* __restrict__ W2) {
    int i = blockIdx.x * blockDim.x + threadIdx.x;
    if (i < DIN_ * D_) {
        float a = W[i], b = W2[i];
        g_Wpack[i] = make_float4(a, a, b, b);
    }
}

__global__ void k_dedup(const int* __restrict__ nodes, const int* __restrict__ edges) {
    int i = blockIdx.x * blockDim.x + threadIdx.x;
    if (i >= NNZ_IN) return;
    int n = __ldg(&nodes[i]), e = __ldg(&edges[i]);
    size_t bit = (size_t)e * N_NODES + (size_t)n;
    unsigned int mask = 1u << (bit & 31);
    unsigned int old = atomicOr(&g_bitmap[bit >> 5], mask);
    if (!(old & mask)) {
        int k = atomicAdd(&g_kept_count, 1);
        g_kept_n[k] = n; g_kept_e[k] = e;
        atomicAdd(&g_deg_e[e], 1);
        atomicAdd(&g_deg_n[n], 1);
    }
}

// scans; node pass also emits w,r (pure functions of node degree)
__global__ void k_scan2() {
    int which = blockIdx.x;
    const int* cnt = which ? g_deg_n : g_deg_e;
    int* rp        = which ? g_rowptr_n : g_rowptr_e;
    int L          = which ? N_NODES : N_EDGES;
    int tid = threadIdx.x, lane = tid & 31, wid = tid >> 5;
    int C = L >> 10;
    int base = tid * C;
    int loc[8];
    int s = 0;
    for (int j = 0; j < C; j++) { loc[j] = cnt[base + j]; s += loc[j]; }
    int ss = s;
#pragma unroll
    for (int o = 1; o < 32; o <<= 1) { int v = __shfl_up_sync(0xffffffffu, ss, o); if (lane >= o) ss += v; }
    __shared__ int wsum[32];
    if (lane == 31) wsum[wid] = ss;
    __syncthreads();
    if (wid == 0) {
        int v = wsum[lane];
#pragma unroll
        for (int o = 1; o < 32; o <<= 1) { int u = __shfl_up_sync(0xffffffffu, v, o); if (lane >= o) v += u; }
        wsum[lane] = v;
    }
    __syncthreads();
    int run = ss - s + (wid ? wsum[wid - 1] : 0);
    for (int j = 0; j < C; j++) { rp[base + j] = run; run += loc[j]; }
    if (tid == 1023) rp[L] = run;
    if (which) {
        for (int j = 0; j < C; j++) {
            int dn = loc[j];
            float g = 1.0f / ((float)N_EDGES + (float)dn * EM1);
            g_w[base + j] = g + (dn == 0 ? (1.0f / N_EDGES) : 0.0f);
            g_r[base + j] = (dn > 0) ? ((float)dn * EM1 * g + 1.0f) : 0.0f;
        }
    }
}

__global__ void k_fill() {
    int i = blockIdx.x * blockDim.x + threadIdx.x;
    int kc = g_kept_count;
    if (i < NNZ_IN) {
        if (i >= kc) return;
        int e = g_kept_e[i];
        int pe = g_rowptr_e[e] + atomicAdd(&g_cur_e[e], 1);
        g_csr_e[pe] = i;
    } else {
        i -= NNZ_IN;
        if (i >= kc) return;
        int n = g_kept_n[i];
        int pn = g_rowptr_n[n] + atomicAdd(&g_cur_n[n], 1);
        g_csr_n[pn] = i;
    }
}

// x4 = x@W2 ; xt = x@W + b ; fused rowv + colsums.
// 512 threads, 4 row-groups of 8; inner loop: 1 LDG.128 (Wpack) + 2 LDS.128 + 8 FFMA2.
__global__ void __launch_bounds__(512) k_gemm_x(const float* __restrict__ x,
                                                const float* __restrict__ bias,
                                                const float* __restrict__ q_ctx) {
    const int ROWS = 32, KC = 32, HR = 8, STRIDE = 36;
    __shared__ __align__(16) float xs[2][KC * STRIDE];
    __shared__ float rvs[ROWS];
    int tid = threadIdx.x;
    int d   = tid & 127;
    int grp = tid >> 7;
    int r0  = blockIdx.x * ROWS;
    int rbase = grp * HR;
    ull a1[HR/2], a2[HR/2];
#pragma unroll
    for (int i = 0; i < HR/2; i++) { a1[i] = 0ull; a2[i] = 0ull; }

#pragma unroll
    for (int t = tid; t < ROWS * KC; t += 512) {
        int rr = t >> 5, cc = t & 31;
        xs[0][cc * STRIDE + rr] = x[(size_t)(r0 + rr) * DIN_ + cc];
    }
    __syncthreads();

    const ulonglong2* wpk = (const ulonglong2*)g_Wpack;

    const int NT = DIN_ / KC;  // 8
    for (int kt = 0; kt < NT; kt++) {
        int cur = kt & 1;
        float pf[2];
        if (kt + 1 < NT) {
            int k0n = (kt + 1) * KC;
#pragma unroll
            for (int t = 0; t < 2; t++) {
                int idx = tid + t * 512;
                int rr = idx >> 5, cc = idx & 31;
                pf[t] = x[(size_t)(r0 + rr) * DIN_ + k0n + cc];
            }
        }
        int k0 = kt * KC;
#pragma unroll
        for (int kk = 0; kk < KC; kk++) {
            ulonglong2 wv = wpk[(size_t)(k0 + kk) * D_ + d];
            const ulonglong2* xp = (const ulonglong2*)&xs[cur][kk * STRIDE + rbase];
#pragma unroll
            for (int rq = 0; rq < HR/4; rq++) {
                ulonglong2 xv = xp[rq];
                ffma2(a1[2*rq    ], xv.x, wv.x);
                ffma2(a1[2*rq + 1], xv.y, wv.x);
                ffma2(a2[2*rq    ], xv.x, wv.y);
                ffma2(a2[2*rq + 1], xv.y, wv.y);
            }
        }
        if (kt + 1 < NT) {
            __syncthreads();
#pragma unroll
            for (int t = 0; t < 2; t++) {
                int idx = tid + t * 512;
                int rr = idx >> 5, cc = idx & 31;
                xs[cur ^ 1][cc * STRIDE + rr] = pf[t];
            }
            __syncthreads();
        }
    }

    if (tid < ROWS) rvs[tid] = 0.f;
    __syncthreads();

    float b = bias[d], q = q_ctx[d];
    float c4 = 0.f, ct = 0.f;
    int lane = tid & 31;
#pragma unroll
    for (int r = 0; r < HR/2; r++) {
        int row = r0 + rbase + 2*r;
        float t0, t1, f0, f1;
        unpack2(a1[r], t0, t1);
        unpack2(a2[r], f0, f1);
        t0 += b; t1 += b;
        g_xt[(size_t)(row    ) * D_ + d] = t0;
        g_xt[(size_t)(row + 1) * D_ + d] = t1;
        g_x4[(size_t)(row    ) * D_ + d] = f0;
        g_x4[(size_t)(row + 1) * D_ + d] = f1;
        ct += t0 + t1;
        c4 += f0 + f1;
        float p0 = f0 * q, p1 = f1 * q;
#pragma unroll
        for (int o = 16; o; o >>= 1) {
            p0 += __shfl_xor_sync(0xffffffffu, p0, o);
            p1 += __shfl_xor_sync(0xffffffffu, p1, o);
        }
        if (lane == 0) {
            atomicAdd(&rvs[rbase + 2*r],     p0);
            atomicAdd(&rvs[rbase + 2*r + 1], p1);
        }
    }
    atomicAdd(&g_s[d],   c4);
    atomicAdd(&g_cxt[d], ct);
    __syncthreads();
    if (tid < ROWS) g_rowv[r0 + tid] = rvs[tid] * INV_TEMP;
}

// per edge: softmax, Pval, u, alpha, v, edge_out, Y.
__global__ void k_edge() {
    int e = blockIdx.x;
    int beg = g_rowptr_e[e], end = g_rowptr_e[e + 1];
    int deg = end - beg;
    float c = 1.0f / ((float)N_NODES + (float)deg * EM1);
    float u = c + (deg == 0 ? (1.0f / N_NODES) : 0.0f);
    __shared__ float red[128];
    __shared__ int   sk[MAXDEG];
    __shared__ int   sn[MAXDEG];
    __shared__ float sp[MAXDEG];
    __shared__ float sacc[4][D_];
    __shared__ float sacy[4][D_];
    int tid = threadIdx.x, lane = tid & 31, wg = tid >> 5;

    for (int j = tid; j < deg; j += 128) {
        int k = g_csr_e[beg + j];
        sk[j] = k;
        sn[j] = g_kept_n[k];
    }
    __syncthreads();

    float m = -INFINITY;
    for (int j = tid; j < deg; j += 128) m = fmaxf(m, g_rowv[sn[j]]);
    red[tid] = m; __syncthreads();
    for (int o = 64; o; o >>= 1) { if (tid < o) red[tid] = fmaxf(red[tid], red[tid + o]); __syncthreads(); }
    m = red[0]; __syncthreads();

    float z = 0.f;
    for (int j = tid; j < deg; j += 128) z += expf(g_rowv[sn[j]] - m);
    red[tid] = z; __syncthreads();
    for (int o = 64; o; o >>= 1) { if (tid < o) red[tid] += red[tid + o]; __syncthreads(); }
    z = red[0];
    float invz = (deg > 0) ? (1.0f / z) : 0.f;

    for (int j = tid; j < deg; j += 128) {
        int n = sn[j];
        float p = EM1 * c + expf(g_rowv[n] - m) * invz;
        sp[j] = p;
        g_Pval[sk[j]] = p;
        atomicAdd(&g_v[n], u * p);
    }
    if (tid == 0) atomicAdd(&g_alpha, u * u);
    __syncthreads();

    float4 at = make_float4(0.f,0.f,0.f,0.f);
    float4 ay = make_float4(0.f,0.f,0.f,0.f);
    for (int j = wg; j < deg; j += 4) {
        size_t roff = (size_t)sn[j] * D_;
        float4 vt = ((const float4*)&g_xt[roff])[lane];
        float4 vy = ((const float4*)&g_x4[roff])[lane];
        float p = sp[j];
        at.x = fmaf(p, vt.x, at.x); at.y = fmaf(p, vt.y, at.y);
        at.z = fmaf(p, vt.z, at.z); at.w = fmaf(p, vt.w, at.w);
        ay.x = fmaf(p, vy.x, ay.x); ay.y = fmaf(p, vy.y, ay.y);
        ay.z = fmaf(p, vy.z, ay.z); ay.w = fmaf(p, vy.w, ay.w);
    }
    ((float4*)&sacc[wg][0])[lane] = at;
    ((float4*)&sacy[wg][0])[lane] = ay;
    __syncthreads();
    int d = tid;
    float acc  = sacc[0][d] + sacc[1][d] + sacc[2][d] + sacc[3][d];
    float accy = sacy[0][d] + sacy[1][d] + sacy[2][d] + sacy[3][d];
    g_edge[(size_t)e * D_ + d] = u * g_cxt[d] + acc;
    g_Y[(size_t)e * D_ + d]    = accy;
}

// edge4 = edge @ W3
__global__ void __launch_bounds__(256) k_gemm_e4(const float* __restrict__ W3) {
    const int ROWS = 16, KC = 32, HR = 8, STRIDE = 20;
    __shared__ __align__(16) float xs[KC * STRIDE];
    int tid = threadIdx.x;
    int d   = tid & 127;
    int grp = tid >> 7;
    int r0  = blockIdx.x * ROWS;
    int rbase = grp * HR;
    ull acc[HR/2];
#pragma unroll
    for (int r = 0; r < HR/2; r++) acc[r] = 0ull;
    for (int k0 = 0; k0 < D_; k0 += KC) {
#pragma unroll
        for (int t = tid; t < ROWS * KC; t += 256) {
            int rr = t >> 5, cc = t & 31;
            xs[cc * STRIDE + rr] = g_edge[(size_t)(r0 + rr) * D_ + k0 + cc];
        }
        __syncthreads();
#pragma unroll
        for (int kk = 0; kk < KC; kk++) {
            ull wp = pack2(W3[(size_t)(k0 + kk) * D_ + d]);
            const ulonglong2* xp = (const ulonglong2*)&xs[kk * STRIDE + rbase];
#pragma unroll
            for (int rq = 0; rq < HR/4; rq++) {
                ulonglong2 xv = xp[rq];
                ffma2(acc[2*rq    ], xv.x, wp);
                ffma2(acc[2*rq + 1], xv.y, wp);
            }
        }
        __syncthreads();
    }
#pragma unroll
    for (int r = 0; r < HR/2; r++) {
        float lo, hi;
        unpack2(acc[r], lo, hi);
        g_edge4[(size_t)(r0 + rbase + 2*r    ) * D_ + d] = lo;
        g_edge4[(size_t)(r0 + rbase + 2*r + 1) * D_ + d] = hi;
    }
}

// fused score + node softmax (warp per node); tail blocks do t/p1/p2 reductions
#define N2F_BLOCKS (N_NODES / 8)
__global__ void k_node2f() {
    if (blockIdx.x >= N2F_BLOCKS) {
        // tail: t/p1/p2 column reductions (v,w,r all ready here)
        int tid = threadIdx.x;
        int d = tid & 127, half = tid >> 7;
        int r0 = (blockIdx.x - N2F_BLOCKS) * 256 + half * 128;
        float t = 0.f, p1 = 0.f, p2 = 0.f;
        for (int r = 0; r < 128; r++) {
            int n = r0 + r;
            float x = g_x4[(size_t)n * D_ + d];
            t  = fmaf(g_v[n], x, t);
            p1 = fmaf(g_w[n], x, p1);
            p2 = fmaf(g_r[n], x, p2);
        }
        atomicAdd(&g_t[d], t);
        atomicAdd(&g_p1[d], p1);
        atomicAdd(&g_p2[d], p2);
        return;
    }
    int n = blockIdx.x * 8 + (threadIdx.x >> 5);
    int lane = threadIdx.x & 31;
    int beg = g_rowptr_n[n], end = g_rowptr_n[n + 1];
    int dn = end - beg;
    float g = 1.0f / ((float)N_EDGES + (float)dn * EM1);

    float4 xv = ((const float4*)&g_x4[(size_t)n * D_])[lane];

    int kreg = (lane < dn) ? g_csr_n[beg + lane] : 0;
    int ereg = (lane < dn) ? g_kept_e[kreg] : 0;

    float m = -INFINITY;
    int dn32 = dn < 32 ? dn : 32;
    for (int j = 0; j < dn32; j++) {
        int k = __shfl_sync(0xffffffffu, kreg, j);
        int e = __shfl_sync(0xffffffffu, ereg, j);
        float4 ev = ((const float4*)&g_edge4[(size_t)e * D_])[lane];
        float s = xv.x*ev.x + xv.y*ev.y + xv.z*ev.z + xv.w*ev.w;
#pragma unroll
        for (int o = 16; o; o >>= 1) s += __shfl_xor_sync(0xffffffffu, s, o);
        s *= INV_TEMP;
        if (lane == 0) g_score[k] = s;
        m = fmaxf(m, s);
    }
    for (int j = 32; j < dn; j++) {
        int k = g_csr_n[beg + j];
        float4 ev = ((const float4*)&g_edge4[(size_t)g_kept_e[k] * D_])[lane];
        float s = xv.x*ev.x + xv.y*ev.y + xv.z*ev.z + xv.w*ev.w;
#pragma unroll
        for (int o = 16; o; o >>= 1) s += __shfl_xor_sync(0xffffffffu, s, o);
        s *= INV_TEMP;
        if (lane == 0) g_score[k] = s;
        m = fmaxf(m, s);
    }
    float z = 0.f;
    for (int j = lane; j < dn; j += 32) z += expf(g_score[g_csr_n[beg + j]] - m);
#pragma unroll
    for (int o = 16; o; o >>= 1) z += __shfl_xor_sync(0xffffffffu, z, o);
    float invz = (dn > 0) ? (1.0f / z) : 0.f;
    for (int j = lane; j < dn; j += 32) {
        int k = g_csr_n[beg + j];
        g_Qval[k] = EM1 * g + expf(g_score[k] - m) * invz;
    }
}

// Y2[e,:] = sum Qval * x4[n,:]
__global__ void k_y2() {
    int e = blockIdx.x, tid = threadIdx.x, lane = tid & 31, wg = tid >> 5;
    int beg = g_rowptr_e[e], end = g_rowptr_e[e + 1];
    int deg = end - beg;
    __shared__ int   sn[MAXDEG];
    __shared__ float sq[MAXDEG];
    __shared__ float sacc[4][D_];
    for (int j = tid; j < deg; j += 128) {
        int k = g_csr_e[beg + j];
        sn[j] = g_kept_n[k];
        sq[j] = g_Qval[k];
    }
    __syncthreads();
    float4 a = make_float4(0.f,0.f,0.f,0.f);
    for (int j = wg; j < deg; j += 4) {
        float4 v = ((const float4*)&g_x4[(size_t)sn[j] * D_])[lane];
        float q = sq[j];
        a.x = fmaf(q, v.x, a.x); a.y = fmaf(q, v.y, a.y);
        a.z = fmaf(q, v.z, a.z); a.w = fmaf(q, v.w, a.w);
    }
    ((float4*)&sacc[wg][0])[lane] = a;
    __syncthreads();
    int d = tid;
    g_Y2[(size_t)e * D_ + d] = sacc[0][d] + sacc[1][d] + sacc[2][d] + sacc[3][d];
}

__global__ void k_final(float* __restrict__ out) {
    int n = blockIdx.x, tid = threadIdx.x, lane = tid & 31, wg = tid >> 5;
    int beg = g_rowptr_n[n], end = g_rowptr_n[n + 1];
    int dn = end - beg;
    __shared__ int   se[MAXDEG];
    __shared__ float spv[MAXDEG];
    __shared__ float sqv[MAXDEG];
    __shared__ float sz1[4][D_];
    __shared__ float sz2[4][D_];
    for (int j = tid; j < dn; j += 128) {
        int k = g_csr_n[beg + j];
        se[j]  = g_kept_e[k];
        spv[j] = g_Pval[k];
        sqv[j] = g_Qval[k];
    }
    __syncthreads();
    float4 a1 = make_float4(0.f,0.f,0.f,0.f);
    float4 a2 = make_float4(0.f,0.f,0.f,0.f);
    for (int j = wg; j < dn; j += 4) {
        size_t roff = (size_t)se[j] * D_;
        float4 v1 = ((const float4*)&g_Y [roff])[lane];
        float4 v2 = ((const float4*)&g_Y2[roff])[lane];
        float p = spv[j], q = sqv[j];
        a1.x = fmaf(p, v1.x, a1.x); a1.y = fmaf(p, v1.y, a1.y);
        a1.z = fmaf(p, v1.z, a1.z); a1.w = fmaf(p, v1.w, a1.w);
        a2.x = fmaf(q, v2.x, a2.x); a2.y = fmaf(q, v2.y, a2.y);
        a2.z = fmaf(q, v2.z, a2.z); a2.w = fmaf(q, v2.w, a2.w);
    }
    ((float4*)&sz1[wg][0])[lane] = a1;
    ((float4*)&sz2[wg][0])[lane] = a2;
    __syncthreads();
    int d = tid;
    float z1 = sz1[0][d] + sz1[1][d] + sz1[2][d] + sz1[3][d];
    float z2 = sz2[0][d] + sz2[1][d] + sz2[2][d] + sz2[3][d];
    float val = (g_alpha + g_v[n]) * g_s[d] + g_t[d]
              + ((float)N_EDGES * g_w[n] + g_r[n]) * g_p1[d]
              + g_w[n] * g_p2[d] + z1 + z2;
    out[(size_t)n * D_ + d] = (val > 0.f) ? val : expm1f(val);
}

// ---------------- launch ----------------
extern "C" void kernel_launch(void* const* d_in, const int* in_sizes, int n_in,
                              void* d_out, int out_size) {
    const float* x      = (const float*)d_in[0];
    const float* W      = (const float*)d_in[1];
    const float* W2     = (const float*)d_in[2];
    const float* W3     = (const float*)d_in[3];
    const float* bias   = (const float*)d_in[4];
    const float* q_ctx  = (const float*)d_in[5];
    const int*   hidx   = (const int*)d_in[6];
    const int* nodes = hidx;
    const int* edges = hidx + NNZ_IN;
    float* out = (float*)d_out;

    static cudaStream_t s_side = nullptr;
    static cudaEvent_t  ev_fork = nullptr, ev_join = nullptr;
    if (s_side == nullptr) {
        cudaStreamCreateWithFlags(&s_side, cudaStreamNonBlocking);
        cudaEventCreateWithFlags(&ev_fork, cudaEventDisableTiming);
        cudaEventCreateWithFlags(&ev_join, cudaEventDisableTiming);
    }

    // fork immediately: side does all index plumbing, main does the GEMM chain
    cudaEventRecord(ev_fork, 0);
    cudaStreamWaitEvent(s_side, ev_fork, 0);

    k_zero_big<<<1024, 256, 0, s_side>>>();
    k_dedup<<<NNZ_IN / 256, 256, 0, s_side>>>(nodes, edges);
    k_scan2<<<2, 1024, 0, s_side>>>();
    k_fill<<<2 * NNZ_IN / 256, 256, 0, s_side>>>();
    cudaEventRecord(ev_join, s_side);

    k_zero_small<<<1, 256>>>();
    k_pack<<<(DIN_ * D_) / 256, 256>>>(W, W2);
    k_gemm_x<<<N_NODES / 32, 512>>>(x, bias, q_ctx);

    cudaStreamWaitEvent(0, ev_join, 0);

    k_edge<<<N_EDGES, 128>>>();
    k_gemm_e4<<<N_EDGES / 16, 256>>>(W3);
    k_node2f<<<N2F_BLOCKS + N_NODES / 256, 256>>>();
    k_y2<<<N_EDGES, 128>>>();
    k_final<<<N_NODES, 128>>>(out);
}

// round 8
// speedup vs baseline: 1.1363x; 1.1363x over previous
#include <cuda_runtime.h>
#include <math.h>

#define N_NODES 8192
#define N_EDGES 4096
#define NNZ_IN  65536
#define DIN_    256
#define D_      128
#define MAXDEG  512

#define EM1     1.7182818284590452f
#define INV_TEMP (1.0f/11.313708498984761f)  // 1/sqrt(128)

typedef unsigned long long ull;

// ---------------- scratch ----------------
__device__ unsigned int g_bitmap[(size_t)N_NODES * N_EDGES / 32];  // 4 MB
__device__ int   g_kept_n[NNZ_IN];
__device__ int   g_kept_e[NNZ_IN];
__device__ int   g_kept_count;
__device__ int   g_deg_e[N_EDGES];
__device__ int   g_deg_n[N_NODES];
__device__ int   g_rowptr_e[N_EDGES + 1];
__device__ int   g_rowptr_n[N_NODES + 1];
__device__ int   g_cur_e[N_EDGES];
__device__ int   g_cur_n[N_NODES];
__device__ int   g_csr_e[NNZ_IN];
__device__ int   g_csr_n[NNZ_IN];
__device__ float g_x4[(size_t)N_NODES * D_];
__device__ float g_xt[(size_t)N_NODES * D_];
__device__ float g_rowv[N_NODES];
__device__ float g_edge[(size_t)N_EDGES * D_];
__device__ float g_edge4[(size_t)N_EDGES * D_];
__device__ float g_Y[(size_t)N_EDGES * D_];
__device__ float g_Y2[(size_t)N_EDGES * D_];
__device__ float g_Pval[NNZ_IN];
__device__ float g_Qval[NNZ_IN];
__device__ float g_score[NNZ_IN];
__device__ float g_v[N_NODES];
__device__ float g_w[N_NODES];
__device__ float g_r[N_NODES];
__device__ float g_s[D_], g_cxt[D_], g_t[D_], g_p1[D_], g_p2[D_];
__device__ float g_alpha;

// ---------------- f32x2 helpers ----------------
__device__ __forceinline__ void ffma2(ull &acc, ull a, ull b) {
    asm("fma.rn.f32x2 %0, %1, %2, %0;" : "+l"(acc) : "l"(a), "l"(b));
}
__device__ __forceinline__ ull pack2(float v) {
    ull r;
    asm("mov.b64 %0, {%1, %1};" : "=l"(r) : "f"(v));
    return r;
}
__device__ __forceinline__ void unpack2(ull a, float &lo, float &hi) {
    asm("mov.b64 {%0, %1}, %2;" : "=f"(lo), "=f"(hi) : "l"(a));
}

// ---------------- kernels ----------------

__global__ void k_zero_small() {
    int i = threadIdx.x;
    if (i < D_) { g_s[i]=0.f; g_cxt[i]=0.f; g_t[i]=0.f; g_p1[i]=0.f; g_p2[i]=0.f; }
    if (i == 0) g_alpha = 0.f;
}

__global__ void k_zero_big() {
    int i = blockIdx.x * blockDim.x + threadIdx.x;
    int stride = gridDim.x * blockDim.x;
    uint4 z4 = make_uint4(0,0,0,0);
    uint4* bm = (uint4*)g_bitmap;
    for (int j = i; j < (int)(sizeof(g_bitmap)/16); j += stride) bm[j] = z4;
    for (int j = i; j < N_EDGES; j += stride) { g_deg_e[j] = 0; g_cur_e[j] = 0; }
    for (int j = i; j < N_NODES; j += stride) { g_deg_n[j] = 0; g_cur_n[j] = 0; g_v[j] = 0.f; }
    if (i == 0) g_kept_count = 0;
}

__global__ void k_dedup(const int* __restrict__ nodes, const int* __restrict__ edges) {
    int i = blockIdx.x * blockDim.x + threadIdx.x;
    if (i >= NNZ_IN) return;
    int n = __ldg(&nodes[i]), e = __ldg(&edges[i]);
    size_t bit = (size_t)e * N_NODES + (size_t)n;
    unsigned int mask = 1u << (bit & 31);
    unsigned int old = atomicOr(&g_bitmap[bit >> 5], mask);
    if (!(old & mask)) {
        int k = atomicAdd(&g_kept_count, 1);
        g_kept_n[k] = n; g_kept_e[k] = e;
        atomicAdd(&g_deg_e[e], 1);
        atomicAdd(&g_deg_n[n], 1);
    }
}

// scans; node pass also emits w,r
__global__ void k_scan2() {
    int which = blockIdx.x;
    const int* cnt = which ? g_deg_n : g_deg_e;
    int* rp        = which ? g_rowptr_n : g_rowptr_e;
    int L          = which ? N_NODES : N_EDGES;
    int tid = threadIdx.x, lane = tid & 31, wid = tid >> 5;
    int C = L >> 10;
    int base = tid * C;
    int loc[8];
    int s = 0;
    for (int j = 0; j < C; j++) { loc[j] = cnt[base + j]; s += loc[j]; }
    int ss = s;
#pragma unroll
    for (int o = 1; o < 32; o <<= 1) { int v = __shfl_up_sync(0xffffffffu, ss, o); if (lane >= o) ss += v; }
    __shared__ int wsum[32];
    if (lane == 31) wsum[wid] = ss;
    __syncthreads();
    if (wid == 0) {
        int v = wsum[lane];
#pragma unroll
        for (int o = 1; o < 32; o <<= 1) { int u = __shfl_up_sync(0xffffffffu, v, o); if (lane >= o) v += u; }
        wsum[lane] = v;
    }
    __syncthreads();
    int run = ss - s + (wid ? wsum[wid - 1] : 0);
    for (int j = 0; j < C; j++) { rp[base + j] = run; run += loc[j]; }
    if (tid == 1023) rp[L] = run;
    if (which) {
        for (int j = 0; j < C; j++) {
            int dn = loc[j];
            float g = 1.0f / ((float)N_EDGES + (float)dn * EM1);
            g_w[base + j] = g + (dn == 0 ? (1.0f / N_EDGES) : 0.0f);
            g_r[base + j] = (dn > 0) ? ((float)dn * EM1 * g + 1.0f) : 0.0f;
        }
    }
}

__global__ void k_fill() {
    int i = blockIdx.x * blockDim.x + threadIdx.x;
    int kc = g_kept_count;
    if (i < NNZ_IN) {
        if (i >= kc) return;
        int e = g_kept_e[i];
        int pe = g_rowptr_e[e] + atomicAdd(&g_cur_e[e], 1);
        g_csr_e[pe] = i;
    } else {
        i -= NNZ_IN;
        if (i >= kc) return;
        int n = g_kept_n[i];
        int pn = g_rowptr_n[n] + atomicAdd(&g_cur_n[n], 1);
        g_csr_n[pn] = i;
    }
}

// x4 = x@W2 ; xt = x@W + b ; fused rowv + colsums (round-6 version: scalar W LDGs)
__global__ void __launch_bounds__(512) k_gemm_x(const float* __restrict__ x,
                                                const float* __restrict__ W,
                                                const float* __restrict__ W2,
                                                const float* __restrict__ bias,
                                                const float* __restrict__ q_ctx) {
    const int ROWS = 32, KC = 32, HR = 8, STRIDE = 36;
    __shared__ __align__(16) float xs[2][KC * STRIDE];
    __shared__ float rvs[ROWS];
    int tid = threadIdx.x;
    int d   = tid & 127;
    int grp = tid >> 7;
    int r0  = blockIdx.x * ROWS;
    int rbase = grp * HR;
    ull a1[HR/2], a2[HR/2];
#pragma unroll
    for (int i = 0; i < HR/2; i++) { a1[i] = 0ull; a2[i] = 0ull; }

#pragma unroll
    for (int t = tid; t < ROWS * KC; t += 512) {
        int rr = t >> 5, cc = t & 31;
        xs[0][cc * STRIDE + rr] = x[(size_t)(r0 + rr) * DIN_ + cc];
    }
    __syncthreads();

    const int NT = DIN_ / KC;  // 8
    for (int kt = 0; kt < NT; kt++) {
        int cur = kt & 1;
        float pf[2];
        if (kt + 1 < NT) {
            int k0n = (kt + 1) * KC;
#pragma unroll
            for (int t = 0; t < 2; t++) {
                int idx = tid + t * 512;
                int rr = idx >> 5, cc = idx & 31;
                pf[t] = x[(size_t)(r0 + rr) * DIN_ + k0n + cc];
            }
        }
        int k0 = kt * KC;
#pragma unroll
        for (int kk = 0; kk < KC; kk++) {
            ull wp  = pack2(W [(size_t)(k0 + kk) * D_ + d]);
            ull w2p = pack2(W2[(size_t)(k0 + kk) * D_ + d]);
            const ulonglong2* xp = (const ulonglong2*)&xs[cur][kk * STRIDE + rbase];
#pragma unroll
            for (int rq = 0; rq < HR/4; rq++) {
                ulonglong2 xv = xp[rq];
                ffma2(a1[2*rq    ], xv.x, wp);
                ffma2(a1[2*rq + 1], xv.y, wp);
                ffma2(a2[2*rq    ], xv.x, w2p);
                ffma2(a2[2*rq + 1], xv.y, w2p);
            }
        }
        if (kt + 1 < NT) {
            __syncthreads();
#pragma unroll
            for (int t = 0; t < 2; t++) {
                int idx = tid + t * 512;
                int rr = idx >> 5, cc = idx & 31;
                xs[cur ^ 1][cc * STRIDE + rr] = pf[t];
            }
            __syncthreads();
        }
    }

    if (tid < ROWS) rvs[tid] = 0.f;
    __syncthreads();

    float b = bias[d], q = q_ctx[d];
    float c4 = 0.f, ct = 0.f;
    int lane = tid & 31;
#pragma unroll
    for (int r = 0; r < HR/2; r++) {
        int row = r0 + rbase + 2*r;
        float t0, t1, f0, f1;
        unpack2(a1[r], t0, t1);
        unpack2(a2[r], f0, f1);
        t0 += b; t1 += b;
        g_xt[(size_t)(row    ) * D_ + d] = t0;
        g_xt[(size_t)(row + 1) * D_ + d] = t1;
        g_x4[(size_t)(row    ) * D_ + d] = f0;
        g_x4[(size_t)(row + 1) * D_ + d] = f1;
        ct += t0 + t1;
        c4 += f0 + f1;
        float p0 = f0 * q, p1 = f1 * q;
#pragma unroll
        for (int o = 16; o; o >>= 1) {
            p0 += __shfl_xor_sync(0xffffffffu, p0, o);
            p1 += __shfl_xor_sync(0xffffffffu, p1, o);
        }
        if (lane == 0) {
            atomicAdd(&rvs[rbase + 2*r],     p0);
            atomicAdd(&rvs[rbase + 2*r + 1], p1);
        }
    }
    atomicAdd(&g_s[d],   c4);
    atomicAdd(&g_cxt[d], ct);
    __syncthreads();
    if (tid < ROWS) g_rowv[r0 + tid] = rvs[tid] * INV_TEMP;
}

// per edge — ONE WARP PER EDGE. lane owns 4 columns (float4).
__global__ void __launch_bounds__(256) k_edge() {
    int lane = threadIdx.x & 31, wid = threadIdx.x >> 5;
    int e = blockIdx.x * 8 + wid;
    int beg = g_rowptr_e[e], end = g_rowptr_e[e + 1];
    int deg = end - beg;
    float c = 1.0f / ((float)N_NODES + (float)deg * EM1);
    float u = c + (deg == 0 ? (1.0f / N_NODES) : 0.0f);

    float m = -INFINITY;
    for (int j = lane; j < deg; j += 32)
        m = fmaxf(m, g_rowv[g_kept_n[g_csr_e[beg + j]]]);
#pragma unroll
    for (int o = 16; o; o >>= 1) m = fmaxf(m, __shfl_xor_sync(0xffffffffu, m, o));

    float z = 0.f;
    for (int j = lane; j < deg; j += 32)
        z += expf(g_rowv[g_kept_n[g_csr_e[beg + j]]] - m);
#pragma unroll
    for (int o = 16; o; o >>= 1) z += __shfl_xor_sync(0xffffffffu, z, o);
    float invz = (deg > 0) ? (1.0f / z) : 0.f;

    float4 at = make_float4(0.f,0.f,0.f,0.f);
    float4 ay = make_float4(0.f,0.f,0.f,0.f);
    for (int j0 = 0; j0 < deg; j0 += 32) {
        int jj = j0 + lane;
        int n = 0; float p = 0.f;
        if (jj < deg) {
            int k = g_csr_e[beg + jj];
            n = g_kept_n[k];
            p = EM1 * c + expf(g_rowv[n] - m) * invz;
            g_Pval[k] = p;
            atomicAdd(&g_v[n], u * p);
        }
        int cnt = deg - j0; if (cnt > 32) cnt = 32;
        for (int t = 0; t < cnt; t++) {
            int   nn = __shfl_sync(0xffffffffu, n, t);
            float pp = __shfl_sync(0xffffffffu, p, t);
            size_t roff = (size_t)nn * D_;
            float4 vt = ((const float4*)&g_xt[roff])[lane];
            float4 vy = ((const float4*)&g_x4[roff])[lane];
            at.x = fmaf(pp, vt.x, at.x); at.y = fmaf(pp, vt.y, at.y);
            at.z = fmaf(pp, vt.z, at.z); at.w = fmaf(pp, vt.w, at.w);
            ay.x = fmaf(pp, vy.x, ay.x); ay.y = fmaf(pp, vy.y, ay.y);
            ay.z = fmaf(pp, vy.z, ay.z); ay.w = fmaf(pp, vy.w, ay.w);
        }
    }
    if (lane == 0) atomicAdd(&g_alpha, u * u);

    float4 cx = ((const float4*)g_cxt)[lane];
    float4 eo = make_float4(fmaf(u, cx.x, at.x), fmaf(u, cx.y, at.y),
                            fmaf(u, cx.z, at.z), fmaf(u, cx.w, at.w));
    ((float4*)&g_edge[(size_t)e * D_])[lane] = eo;
    ((float4*)&g_Y  [(size_t)e * D_])[lane] = ay;
}

// edge4 = edge @ W3
__global__ void __launch_bounds__(256) k_gemm_e4(const float* __restrict__ W3) {
    const int ROWS = 16, KC = 32, HR = 8, STRIDE = 20;
    __shared__ __align__(16) float xs[KC * STRIDE];
    int tid = threadIdx.x;
    int d   = tid & 127;
    int grp = tid >> 7;
    int r0  = blockIdx.x * ROWS;
    int rbase = grp * HR;
    ull acc[HR/2];
#pragma unroll
    for (int r = 0; r < HR/2; r++) acc[r] = 0ull;
    for (int k0 = 0; k0 < D_; k0 += KC) {
#pragma unroll
        for (int t = tid; t < ROWS * KC; t += 256) {
            int rr = t >> 5, cc = t & 31;
            xs[cc * STRIDE + rr] = g_edge[(size_t)(r0 + rr) * D_ + k0 + cc];
        }
        __syncthreads();
#pragma unroll
        for (int kk = 0; kk < KC; kk++) {
            ull wp = pack2(W3[(size_t)(k0 + kk) * D_ + d]);
            const ulonglong2* xp = (const ulonglong2*)&xs[kk * STRIDE + rbase];
#pragma unroll
            for (int rq = 0; rq < HR/4; rq++) {
                ulonglong2 xv = xp[rq];
                ffma2(acc[2*rq    ], xv.x, wp);
                ffma2(acc[2*rq + 1], xv.y, wp);
            }
        }
        __syncthreads();
    }
#pragma unroll
    for (int r = 0; r < HR/2; r++) {
        float lo, hi;
        unpack2(acc[r], lo, hi);
        g_edge4[(size_t)(r0 + rbase + 2*r    ) * D_ + d] = lo;
        g_edge4[(size_t)(r0 + rbase + 2*r + 1) * D_ + d] = hi;
    }
}

// fused score + node softmax (warp per node); tail blocks: t/p1/p2 reductions
#define N2F_BLOCKS (N_NODES / 8)
__global__ void k_node2f() {
    if (blockIdx.x >= N2F_BLOCKS) {
        int tid = threadIdx.x;
        int d = tid & 127, half = tid >> 7;
        int r0 = (blockIdx.x - N2F_BLOCKS) * 256 + half * 128;
        float t = 0.f, p1 = 0.f, p2 = 0.f;
        for (int r = 0; r < 128; r++) {
            int n = r0 + r;
            float x = g_x4[(size_t)n * D_ + d];
            t  = fmaf(g_v[n], x, t);
            p1 = fmaf(g_w[n], x, p1);
            p2 = fmaf(g_r[n], x, p2);
        }
        atomicAdd(&g_t[d], t);
        atomicAdd(&g_p1[d], p1);
        atomicAdd(&g_p2[d], p2);
        return;
    }
    int n = blockIdx.x * 8 + (threadIdx.x >> 5);
    int lane = threadIdx.x & 31;
    int beg = g_rowptr_n[n], end = g_rowptr_n[n + 1];
    int dn = end - beg;
    float g = 1.0f / ((float)N_EDGES + (float)dn * EM1);

    float4 xv = ((const float4*)&g_x4[(size_t)n * D_])[lane];

    int kreg = (lane < dn) ? g_csr_n[beg + lane] : 0;
    int ereg = (lane < dn) ? g_kept_e[kreg] : 0;

    float m = -INFINITY;
    int dn32 = dn < 32 ? dn : 32;
    for (int j = 0; j < dn32; j++) {
        int k = __shfl_sync(0xffffffffu, kreg, j);
        int e = __shfl_sync(0xffffffffu, ereg, j);
        float4 ev = ((const float4*)&g_edge4[(size_t)e * D_])[lane];
        float s = xv.x*ev.x + xv.y*ev.y + xv.z*ev.z + xv.w*ev.w;
#pragma unroll
        for (int o = 16; o; o >>= 1) s += __shfl_xor_sync(0xffffffffu, s, o);
        s *= INV_TEMP;
        if (lane == 0) g_score[k] = s;
        m = fmaxf(m, s);
    }
    for (int j = 32; j < dn; j++) {
        int k = g_csr_n[beg + j];
        float4 ev = ((const float4*)&g_edge4[(size_t)g_kept_e[k] * D_])[lane];
        float s = xv.x*ev.x + xv.y*ev.y + xv.z*ev.z + xv.w*ev.w;
#pragma unroll
        for (int o = 16; o; o >>= 1) s += __shfl_xor_sync(0xffffffffu, s, o);
        s *= INV_TEMP;
        if (lane == 0) g_score[k] = s;
        m = fmaxf(m, s);
    }
    float z = 0.f;
    for (int j = lane; j < dn; j += 32) z += expf(g_score[g_csr_n[beg + j]] - m);
#pragma unroll
    for (int o = 16; o; o >>= 1) z += __shfl_xor_sync(0xffffffffu, z, o);
    float invz = (dn > 0) ? (1.0f / z) : 0.f;
    for (int j = lane; j < dn; j += 32) {
        int k = g_csr_n[beg + j];
        g_Qval[k] = EM1 * g + expf(g_score[k] - m) * invz;
    }
}

// Y2 — ONE WARP PER EDGE
__global__ void __launch_bounds__(256) k_y2() {
    int lane = threadIdx.x & 31, wid = threadIdx.x >> 5;
    int e = blockIdx.x * 8 + wid;
    int beg = g_rowptr_e[e], end = g_rowptr_e[e + 1];
    int deg = end - beg;
    float4 a = make_float4(0.f,0.f,0.f,0.f);
    for (int j0 = 0; j0 < deg; j0 += 32) {
        int jj = j0 + lane;
        int n = 0; float q = 0.f;
        if (jj < deg) {
            int k = g_csr_e[beg + jj];
            n = g_kept_n[k];
            q = g_Qval[k];
        }
        int cnt = deg - j0; if (cnt > 32) cnt = 32;
        for (int t = 0; t < cnt; t++) {
            int   nn = __shfl_sync(0xffffffffu, n, t);
            float qq = __shfl_sync(0xffffffffu, q, t);
            float4 v = ((const float4*)&g_x4[(size_t)nn * D_])[lane];
            a.x = fmaf(qq, v.x, a.x); a.y = fmaf(qq, v.y, a.y);
            a.z = fmaf(qq, v.z, a.z); a.w = fmaf(qq, v.w, a.w);
        }
    }
    ((float4*)&g_Y2[(size_t)e * D_])[lane] = a;
}

// final — ONE WARP PER NODE
__global__ void __launch_bounds__(256) k_final(float* __restrict__ out) {
    int lane = threadIdx.x & 31, wid = threadIdx.x >> 5;
    int n = blockIdx.x * 8 + wid;
    int beg = g_rowptr_n[n], end = g_rowptr_n[n + 1];
    int dn = end - beg;
    float4 a1 = make_float4(0.f,0.f,0.f,0.f);
    float4 a2 = make_float4(0.f,0.f,0.f,0.f);
    for (int j0 = 0; j0 < dn; j0 += 32) {
        int jj = j0 + lane;
        int e = 0; float p = 0.f, q = 0.f;
        if (jj < dn) {
            int k = g_csr_n[beg + jj];
            e = g_kept_e[k];
            p = g_Pval[k];
            q = g_Qval[k];
        }
        int cnt = dn - j0; if (cnt > 32) cnt = 32;
        for (int t = 0; t < cnt; t++) {
            int   ee = __shfl_sync(0xffffffffu, e, t);
            float pp = __shfl_sync(0xffffffffu, p, t);
            float qq = __shfl_sync(0xffffffffu, q, t);
            size_t roff = (size_t)ee * D_;
            float4 v1 = ((const float4*)&g_Y [roff])[lane];
            float4 v2 = ((const float4*)&g_Y2[roff])[lane];
            a1.x = fmaf(pp, v1.x, a1.x); a1.y = fmaf(pp, v1.y, a1.y);
            a1.z = fmaf(pp, v1.z, a1.z); a1.w = fmaf(pp, v1.w, a1.w);
            a2.x = fmaf(qq, v2.x, a2.x); a2.y = fmaf(qq, v2.y, a2.y);
            a2.z = fmaf(qq, v2.z, a2.z); a2.w = fmaf(qq, v2.w, a2.w);
        }
    }
    float av = g_alpha + g_v[n];
    float wn = g_w[n];
    float cw = (float)N_EDGES * wn + g_r[n];
    float4 sv = ((const float4*)g_s )[lane];
    float4 tv = ((const float4*)g_t )[lane];
    float4 pv = ((const float4*)g_p1)[lane];
    float4 qv = ((const float4*)g_p2)[lane];
    float4 r;
    r.x = av*sv.x + tv.x + cw*pv.x + wn*qv.x + a1.x + a2.x;
    r.y = av*sv.y + tv.y + cw*pv.y + wn*qv.y + a1.y + a2.y;
    r.z = av*sv.z + tv.z + cw*pv.z + wn*qv.z + a1.z + a2.z;
    r.w = av*sv.w + tv.w + cw*pv.w + wn*qv.w + a1.w + a2.w;
    r.x = (r.x > 0.f) ? r.x : expm1f(r.x);
    r.y = (r.y > 0.f) ? r.y : expm1f(r.y);
    r.z = (r.z > 0.f) ? r.z : expm1f(r.z);
    r.w = (r.w > 0.f) ? r.w : expm1f(r.w);
    ((float4*)&out[(size_t)n * D_])[lane] = r;
}

// ---------------- launch ----------------
extern "C" void kernel_launch(void* const* d_in, const int* in_sizes, int n_in,
                              void* d_out, int out_size) {
    const float* x      = (const float*)d_in[0];
    const float* W      = (const float*)d_in[1];
    const float* W2     = (const float*)d_in[2];
    const float* W3     = (const float*)d_in[3];
    const float* bias   = (const float*)d_in[4];
    const float* q_ctx  = (const float*)d_in[5];
    const int*   hidx   = (const int*)d_in[6];
    const int* nodes = hidx;
    const int* edges = hidx + NNZ_IN;
    float* out = (float*)d_out;

    static cudaStream_t s_side = nullptr;
    static cudaEvent_t  ev_fork = nullptr, ev_join = nullptr;
    if (s_side == nullptr) {
        cudaStreamCreateWithFlags(&s_side, cudaStreamNonBlocking);
        cudaEventCreateWithFlags(&ev_fork, cudaEventDisableTiming);
        cudaEventCreateWithFlags(&ev_join, cudaEventDisableTiming);
    }

    cudaEventRecord(ev_fork, 0);
    cudaStreamWaitEvent(s_side, ev_fork, 0);

    k_zero_big<<<1024, 256, 0, s_side>>>();
    k_dedup<<<NNZ_IN / 256, 256, 0, s_side>>>(nodes, edges);
    k_scan2<<<2, 1024, 0, s_side>>>();
    k_fill<<<2 * NNZ_IN / 256, 256, 0, s_side>>>();
    cudaEventRecord(ev_join, s_side);

    k_zero_small<<<1, 256>>>();
    k_gemm_x<<<N_NODES / 32, 512>>>(x, W, W2, bias, q_ctx);

    cudaStreamWaitEvent(0, ev_join, 0);

    k_edge<<<N_EDGES / 8, 256>>>();
    k_gemm_e4<<<N_EDGES / 16, 256>>>(W3);
    k_node2f<<<N2F_BLOCKS + N_NODES / 256, 256>>>();
    k_y2<<<N_EDGES / 8, 256>>>();
    k_final<<<N_NODES / 8, 256>>>(out);
}

// round 9
// speedup vs baseline: 1.2367x; 1.0883x over previous
#include <cuda_runtime.h>
#include <math.h>

#define N_NODES 8192
#define N_EDGES 4096
#define NNZ_IN  65536
#define DIN_    256
#define D_      128

#define EM1     1.7182818284590452f
#define INV_TEMP (1.0f/11.313708498984761f)  // 1/sqrt(128)

typedef unsigned long long ull;

// ---------------- scratch ----------------
__device__ unsigned int g_bitmap[(size_t)N_NODES * N_EDGES / 32];  // 4 MB
__device__ int   g_kept_n[NNZ_IN];
__device__ int   g_kept_e[NNZ_IN];
__device__ int   g_kept_count;
__device__ int   g_deg_e[N_EDGES];
__device__ int   g_deg_n[N_NODES];
__device__ int   g_rowptr_e[N_EDGES + 1];
__device__ int   g_rowptr_n[N_NODES + 1];
__device__ int   g_cur_e[N_EDGES];
__device__ int   g_cur_n[N_NODES];
__device__ int   g_csr_e[NNZ_IN];
__device__ int   g_csr_n[NNZ_IN];
__device__ float g_x4[(size_t)N_NODES * D_];
__device__ float g_xt[(size_t)N_NODES * D_];
__device__ float g_rowv[N_NODES];
__device__ float g_edge4[(size_t)N_EDGES * D_];
__device__ float g_Y[(size_t)N_EDGES * D_];
__device__ float g_Y2[(size_t)N_EDGES * D_];
__device__ float g_Pval[NNZ_IN];
__device__ float g_Qval[NNZ_IN];
__device__ float g_score[NNZ_IN];
__device__ float g_v[N_NODES];
__device__ float g_w[N_NODES];
__device__ float g_r[N_NODES];
__device__ float g_s[D_], g_cxt[D_], g_t[D_], g_p1[D_], g_p2[D_];
__device__ float g_alpha;

// ---------------- f32x2 helpers ----------------
__device__ __forceinline__ void ffma2(ull &acc, ull a, ull b) {
    asm("fma.rn.f32x2 %0, %1, %2, %0;" : "+l"(acc) : "l"(a), "l"(b));
}
__device__ __forceinline__ ull pack2(float v) {
    ull r;
    asm("mov.b64 %0, {%1, %1};" : "=l"(r) : "f"(v));
    return r;
}
__device__ __forceinline__ void unpack2(ull a, float &lo, float &hi) {
    asm("mov.b64 {%0, %1}, %2;" : "=f"(lo), "=f"(hi) : "l"(a));
}

// ---------------- kernels ----------------

__global__ void k_zero_small() {
    int i = threadIdx.x;
    if (i < D_) { g_s[i]=0.f; g_cxt[i]=0.f; g_t[i]=0.f; g_p1[i]=0.f; g_p2[i]=0.f; }
    if (i == 0) g_alpha = 0.f;
}

__global__ void k_zero_big() {
    int i = blockIdx.x * blockDim.x + threadIdx.x;
    int stride = gridDim.x * blockDim.x;
    uint4 z4 = make_uint4(0,0,0,0);
    uint4* bm = (uint4*)g_bitmap;
    for (int j = i; j < (int)(sizeof(g_bitmap)/16); j += stride) bm[j] = z4;
    for (int j = i; j < N_EDGES; j += stride) { g_deg_e[j] = 0; g_cur_e[j] = 0; }
    for (int j = i; j < N_NODES; j += stride) { g_deg_n[j] = 0; g_cur_n[j] = 0; g_v[j] = 0.f; }
    if (i == 0) g_kept_count = 0;
}

__global__ void k_dedup(const int* __restrict__ nodes, const int* __restrict__ edges) {
    int i = blockIdx.x * blockDim.x + threadIdx.x;
    if (i >= NNZ_IN) return;
    int n = __ldg(&nodes[i]), e = __ldg(&edges[i]);
    size_t bit = (size_t)e * N_NODES + (size_t)n;
    unsigned int mask = 1u << (bit & 31);
    unsigned int old = atomicOr(&g_bitmap[bit >> 5], mask);
    if (!(old & mask)) {
        int k = atomicAdd(&g_kept_count, 1);
        g_kept_n[k] = n; g_kept_e[k] = e;
        atomicAdd(&g_deg_e[e], 1);
        atomicAdd(&g_deg_n[n], 1);
    }
}

// scans; node pass also emits w,r
__global__ void k_scan2() {
    int which = blockIdx.x;
    const int* cnt = which ? g_deg_n : g_deg_e;
    int* rp        = which ? g_rowptr_n : g_rowptr_e;
    int L          = which ? N_NODES : N_EDGES;
    int tid = threadIdx.x, lane = tid & 31, wid = tid >> 5;
    int C = L >> 10;
    int base = tid * C;
    int loc[8];
    int s = 0;
    for (int j = 0; j < C; j++) { loc[j] = cnt[base + j]; s += loc[j]; }
    int ss = s;
#pragma unroll
    for (int o = 1; o < 32; o <<= 1) { int v = __shfl_up_sync(0xffffffffu, ss, o); if (lane >= o) ss += v; }
    __shared__ int wsum[32];
    if (lane == 31) wsum[wid] = ss;
    __syncthreads();
    if (wid == 0) {
        int v = wsum[lane];
#pragma unroll
        for (int o = 1; o < 32; o <<= 1) { int u = __shfl_up_sync(0xffffffffu, v, o); if (lane >= o) v += u; }
        wsum[lane] = v;
    }
    __syncthreads();
    int run = ss - s + (wid ? wsum[wid - 1] : 0);
    for (int j = 0; j < C; j++) { rp[base + j] = run; run += loc[j]; }
    if (tid == 1023) rp[L] = run;
    if (which) {
        for (int j = 0; j < C; j++) {
            int dn = loc[j];
            float g = 1.0f / ((float)N_EDGES + (float)dn * EM1);
            g_w[base + j] = g + (dn == 0 ? (1.0f / N_EDGES) : 0.0f);
            g_r[base + j] = (dn > 0) ? ((float)dn * EM1 * g + 1.0f) : 0.0f;
        }
    }
}

__global__ void k_fill() {
    int i = blockIdx.x * blockDim.x + threadIdx.x;
    int kc = g_kept_count;
    if (i < NNZ_IN) {
        if (i >= kc) return;
        int e = g_kept_e[i];
        int pe = g_rowptr_e[e] + atomicAdd(&g_cur_e[e], 1);
        g_csr_e[pe] = i;
    } else {
        i -= NNZ_IN;
        if (i >= kc) return;
        int n = g_kept_n[i];
        int pn = g_rowptr_n[n] + atomicAdd(&g_cur_n[n], 1);
        g_csr_n[pn] = i;
    }
}

// x4 = x@W2 ; xt = x@W + b ; fused rowv + colsums.
// __launch_bounds__(512,2): cap regs at 64 so 2 blocks (32 warps) co-reside per SM.
__global__ void __launch_bounds__(512, 2) k_gemm_x(const float* __restrict__ x,
                                                   const float* __restrict__ W,
                                                   const float* __restrict__ W2,
                                                   const float* __restrict__ bias,
                                                   const float* __restrict__ q_ctx) {
    const int ROWS = 32, KC = 32, HR = 8, STRIDE = 36;
    __shared__ __align__(16) float xs[2][KC * STRIDE];
    __shared__ float rvs[ROWS];
    int tid = threadIdx.x;
    int d   = tid & 127;
    int grp = tid >> 7;
    int r0  = blockIdx.x * ROWS;
    int rbase = grp * HR;
    ull a1[HR/2], a2[HR/2];
#pragma unroll
    for (int i = 0; i < HR/2; i++) { a1[i] = 0ull; a2[i] = 0ull; }

#pragma unroll
    for (int t = tid; t < ROWS * KC; t += 512) {
        int rr = t >> 5, cc = t & 31;
        xs[0][cc * STRIDE + rr] = x[(size_t)(r0 + rr) * DIN_ + cc];
    }
    __syncthreads();

    const int NT = DIN_ / KC;  // 8
    for (int kt = 0; kt < NT; kt++) {
        int cur = kt & 1;
        float pf[2];
        if (kt + 1 < NT) {
            int k0n = (kt + 1) * KC;
#pragma unroll
            for (int t = 0; t < 2; t++) {
                int idx = tid + t * 512;
                int rr = idx >> 5, cc = idx & 31;
                pf[t] = x[(size_t)(r0 + rr) * DIN_ + k0n + cc];
            }
        }
        int k0 = kt * KC;
#pragma unroll
        for (int kk = 0; kk < KC; kk++) {
            ull wp  = pack2(W [(size_t)(k0 + kk) * D_ + d]);
            ull w2p = pack2(W2[(size_t)(k0 + kk) * D_ + d]);
            const ulonglong2* xp = (const ulonglong2*)&xs[cur][kk * STRIDE + rbase];
#pragma unroll
            for (int rq = 0; rq < HR/4; rq++) {
                ulonglong2 xv = xp[rq];
                ffma2(a1[2*rq    ], xv.x, wp);
                ffma2(a1[2*rq + 1], xv.y, wp);
                ffma2(a2[2*rq    ], xv.x, w2p);
                ffma2(a2[2*rq + 1], xv.y, w2p);
            }
        }
        if (kt + 1 < NT) {
            __syncthreads();
#pragma unroll
            for (int t = 0; t < 2; t++) {
                int idx = tid + t * 512;
                int rr = idx >> 5, cc = idx & 31;
                xs[cur ^ 1][cc * STRIDE + rr] = pf[t];
            }
            __syncthreads();
        }
    }

    if (tid < ROWS) rvs[tid] = 0.f;
    __syncthreads();

    float b = bias[d], q = q_ctx[d];
    float c4 = 0.f, ct = 0.f;
    int lane = tid & 31;
#pragma unroll
    for (int r = 0; r < HR/2; r++) {
        int row = r0 + rbase + 2*r;
        float t0, t1, f0, f1;
        unpack2(a1[r], t0, t1);
        unpack2(a2[r], f0, f1);
        t0 += b; t1 += b;
        g_xt[(size_t)(row    ) * D_ + d] = t0;
        g_xt[(size_t)(row + 1) * D_ + d] = t1;
        g_x4[(size_t)(row    ) * D_ + d] = f0;
        g_x4[(size_t)(row + 1) * D_ + d] = f1;
        ct += t0 + t1;
        c4 += f0 + f1;
        float p0 = f0 * q, p1 = f1 * q;
#pragma unroll
        for (int o = 16; o; o >>= 1) {
            p0 += __shfl_xor_sync(0xffffffffu, p0, o);
            p1 += __shfl_xor_sync(0xffffffffu, p1, o);
        }
        if (lane == 0) {
            atomicAdd(&rvs[rbase + 2*r],     p0);
            atomicAdd(&rvs[rbase + 2*r + 1], p1);
        }
    }
    atomicAdd(&g_s[d],   c4);
    atomicAdd(&g_cxt[d], ct);
    __syncthreads();
    if (tid < ROWS) g_rowv[r0 + tid] = rvs[tid] * INV_TEMP;
}

// per edge (warp per edge) + FUSED edge4 = edge @ W3 block mini-GEMM.
__global__ void __launch_bounds__(256) k_edge(const float* __restrict__ W3) {
    __shared__ __align__(16) float se[8][132];   // edge vectors (eo), row stride 132
    int tid = threadIdx.x, lane = tid & 31, wid = tid >> 5;
    int e = blockIdx.x * 8 + wid;
    int beg = g_rowptr_e[e], end = g_rowptr_e[e + 1];
    int deg = end - beg;
    float c = 1.0f / ((float)N_NODES + (float)deg * EM1);
    float u = c + (deg == 0 ? (1.0f / N_NODES) : 0.0f);

    float m = -INFINITY;
    for (int j = lane; j < deg; j += 32)
        m = fmaxf(m, g_rowv[g_kept_n[g_csr_e[beg + j]]]);
#pragma unroll
    for (int o = 16; o; o >>= 1) m = fmaxf(m, __shfl_xor_sync(0xffffffffu, m, o));

    float z = 0.f;
    for (int j = lane; j < deg; j += 32)
        z += expf(g_rowv[g_kept_n[g_csr_e[beg + j]]] - m);
#pragma unroll
    for (int o = 16; o; o >>= 1) z += __shfl_xor_sync(0xffffffffu, z, o);
    float invz = (deg > 0) ? (1.0f / z) : 0.f;

    float4 at = make_float4(0.f,0.f,0.f,0.f);
    float4 ay = make_float4(0.f,0.f,0.f,0.f);
    for (int j0 = 0; j0 < deg; j0 += 32) {
        int jj = j0 + lane;
        int n = 0; float p = 0.f;
        if (jj < deg) {
            int k = g_csr_e[beg + jj];
            n = g_kept_n[k];
            p = EM1 * c + expf(g_rowv[n] - m) * invz;
            g_Pval[k] = p;
            atomicAdd(&g_v[n], u * p);
        }
        int cnt = deg - j0; if (cnt > 32) cnt = 32;
        for (int t = 0; t < cnt; t++) {
            int   nn = __shfl_sync(0xffffffffu, n, t);
            float pp = __shfl_sync(0xffffffffu, p, t);
            size_t roff = (size_t)nn * D_;
            float4 vt = ((const float4*)&g_xt[roff])[lane];
            float4 vy = ((const float4*)&g_x4[roff])[lane];
            at.x = fmaf(pp, vt.x, at.x); at.y = fmaf(pp, vt.y, at.y);
            at.z = fmaf(pp, vt.z, at.z); at.w = fmaf(pp, vt.w, at.w);
            ay.x = fmaf(pp, vy.x, ay.x); ay.y = fmaf(pp, vy.y, ay.y);
            ay.z = fmaf(pp, vy.z, ay.z); ay.w = fmaf(pp, vy.w, ay.w);
        }
    }
    if (lane == 0) atomicAdd(&g_alpha, u * u);

    float4 cx = ((const float4*)g_cxt)[lane];
    float4 eo = make_float4(fmaf(u, cx.x, at.x), fmaf(u, cx.y, at.y),
                            fmaf(u, cx.z, at.z), fmaf(u, cx.w, at.w));
    ((float4*)&g_Y[(size_t)e * D_])[lane] = ay;
    *((float4*)&se[wid][lane * 4]) = eo;
    __syncthreads();

    // mini-GEMM: edge4[8 x 128] = se[8 x 128] @ W3[128 x 128]
    // thread (sub,d): sub = tid>>7 owns edges sub*4..sub*4+3, column d.
    int d = tid & 127, sub = tid >> 7;
    const float* w3c = W3 + d;
    const float* r0p = &se[sub*4 + 0][0];
    const float* r1p = &se[sub*4 + 1][0];
    const float* r2p = &se[sub*4 + 2][0];
    const float* r3p = &se[sub*4 + 3][0];
    float a0 = 0.f, b0 = 0.f, c0 = 0.f, d0 = 0.f;
#pragma unroll 8
    for (int k = 0; k < D_; k += 4) {
        float4 e0 = *(const float4*)&r0p[k];
        float4 e1 = *(const float4*)&r1p[k];
        float4 e2 = *(const float4*)&r2p[k];
        float4 e3 = *(const float4*)&r3p[k];
        float w0 = w3c[(k+0)*D_], w1 = w3c[(k+1)*D_];
        float w2 = w3c[(k+2)*D_], w3v = w3c[(k+3)*D_];
        a0 = fmaf(e0.x,w0,fmaf(e0.y,w1,fmaf(e0.z,w2,fmaf(e0.w,w3v,a0))));
        b0 = fmaf(e1.x,w0,fmaf(e1.y,w1,fmaf(e1.z,w2,fmaf(e1.w,w3v,b0))));
        c0 = fmaf(e2.x,w0,fmaf(e2.y,w1,fmaf(e2.z,w2,fmaf(e2.w,w3v,c0))));
        d0 = fmaf(e3.x,w0,fmaf(e3.y,w1,fmaf(e3.z,w2,fmaf(e3.w,w3v,d0))));
    }
    int ebase = blockIdx.x * 8 + sub * 4;
    g_edge4[(size_t)(ebase + 0) * D_ + d] = a0;
    g_edge4[(size_t)(ebase + 1) * D_ + d] = b0;
    g_edge4[(size_t)(ebase + 2) * D_ + d] = c0;
    g_edge4[(size_t)(ebase + 3) * D_ + d] = d0;
}

// fused score + node softmax (warp per node); tail blocks: t/p1/p2 reductions
#define N2F_BLOCKS (N_NODES / 8)
__global__ void k_node2f() {
    if (blockIdx.x >= N2F_BLOCKS) {
        int tid = threadIdx.x;
        int d = tid & 127, half = tid >> 7;
        int r0 = (blockIdx.x - N2F_BLOCKS) * 256 + half * 128;
        float t = 0.f, p1 = 0.f, p2 = 0.f;
        for (int r = 0; r < 128; r++) {
            int n = r0 + r;
            float x = g_x4[(size_t)n * D_ + d];
            t  = fmaf(g_v[n], x, t);
            p1 = fmaf(g_w[n], x, p1);
            p2 = fmaf(g_r[n], x, p2);
        }
        atomicAdd(&g_t[d], t);
        atomicAdd(&g_p1[d], p1);
        atomicAdd(&g_p2[d], p2);
        return;
    }
    int n = blockIdx.x * 8 + (threadIdx.x >> 5);
    int lane = threadIdx.x & 31;
    int beg = g_rowptr_n[n], end = g_rowptr_n[n + 1];
    int dn = end - beg;
    float g = 1.0f / ((float)N_EDGES + (float)dn * EM1);

    float4 xv = ((const float4*)&g_x4[(size_t)n * D_])[lane];

    int kreg = (lane < dn) ? g_csr_n[beg + lane] : 0;
    int ereg = (lane < dn) ? g_kept_e[kreg] : 0;

    float m = -INFINITY;
    int dn32 = dn < 32 ? dn : 32;
    for (int j = 0; j < dn32; j++) {
        int k = __shfl_sync(0xffffffffu, kreg, j);
        int e = __shfl_sync(0xffffffffu, ereg, j);
        float4 ev = ((const float4*)&g_edge4[(size_t)e * D_])[lane];
        float s = xv.x*ev.x + xv.y*ev.y + xv.z*ev.z + xv.w*ev.w;
#pragma unroll
        for (int o = 16; o; o >>= 1) s += __shfl_xor_sync(0xffffffffu, s, o);
        s *= INV_TEMP;
        if (lane == 0) g_score[k] = s;
        m = fmaxf(m, s);
    }
    for (int j = 32; j < dn; j++) {
        int k = g_csr_n[beg + j];
        float4 ev = ((const float4*)&g_edge4[(size_t)g_kept_e[k] * D_])[lane];
        float s = xv.x*ev.x + xv.y*ev.y + xv.z*ev.z + xv.w*ev.w;
#pragma unroll
        for (int o = 16; o; o >>= 1) s += __shfl_xor_sync(0xffffffffu, s, o);
        s *= INV_TEMP;
        if (lane == 0) g_score[k] = s;
        m = fmaxf(m, s);
    }
    float z = 0.f;
    for (int j = lane; j < dn; j += 32) z += expf(g_score[g_csr_n[beg + j]] - m);
#pragma unroll
    for (int o = 16; o; o >>= 1) z += __shfl_xor_sync(0xffffffffu, z, o);
    float invz = (dn > 0) ? (1.0f / z) : 0.f;
    for (int j = lane; j < dn; j += 32) {
        int k = g_csr_n[beg + j];
        g_Qval[k] = EM1 * g + expf(g_score[k] - m) * invz;
    }
}

// Y2 — one warp per edge
__global__ void __launch_bounds__(256) k_y2() {
    int lane = threadIdx.x & 31, wid = threadIdx.x >> 5;
    int e = blockIdx.x * 8 + wid;
    int beg = g_rowptr_e[e], end = g_rowptr_e[e + 1];
    int deg = end - beg;
    float4 a = make_float4(0.f,0.f,0.f,0.f);
    for (int j0 = 0; j0 < deg; j0 += 32) {
        int jj = j0 + lane;
        int n = 0; float q = 0.f;
        if (jj < deg) {
            int k = g_csr_e[beg + jj];
            n = g_kept_n[k];
            q = g_Qval[k];
        }
        int cnt = deg - j0; if (cnt > 32) cnt = 32;
        for (int t = 0; t < cnt; t++) {
            int   nn = __shfl_sync(0xffffffffu, n, t);
            float qq = __shfl_sync(0xffffffffu, q, t);
            float4 v = ((const float4*)&g_x4[(size_t)nn * D_])[lane];
            a.x = fmaf(qq, v.x, a.x); a.y = fmaf(qq, v.y, a.y);
            a.z = fmaf(qq, v.z, a.z); a.w = fmaf(qq, v.w, a.w);
        }
    }
    ((float4*)&g_Y2[(size_t)e * D_])[lane] = a;
}

// final — one warp per node
__global__ void __launch_bounds__(256) k_final(float* __restrict__ out) {
    int lane = threadIdx.x & 31, wid = threadIdx.x >> 5;
    int n = blockIdx.x * 8 + wid;
    int beg = g_rowptr_n[n], end = g_rowptr_n[n + 1];
    int dn = end - beg;
    float4 a1 = make_float4(0.f,0.f,0.f,0.f);
    float4 a2 = make_float4(0.f,0.f,0.f,0.f);
    for (int j0 = 0; j0 < dn; j0 += 32) {
        int jj = j0 + lane;
        int e = 0; float p = 0.f, q = 0.f;
        if (jj < dn) {
            int k = g_csr_n[beg + jj];
            e = g_kept_e[k];
            p = g_Pval[k];
            q = g_Qval[k];
        }
        int cnt = dn - j0; if (cnt > 32) cnt = 32;
        for (int t = 0; t < cnt; t++) {
            int   ee = __shfl_sync(0xffffffffu, e, t);
            float pp = __shfl_sync(0xffffffffu, p, t);
            float qq = __shfl_sync(0xffffffffu, q, t);
            size_t roff = (size_t)ee * D_;
            float4 v1 = ((const float4*)&g_Y [roff])[lane];
            float4 v2 = ((const float4*)&g_Y2[roff])[lane];
            a1.x = fmaf(pp, v1.x, a1.x); a1.y = fmaf(pp, v1.y, a1.y);
            a1.z = fmaf(pp, v1.z, a1.z); a1.w = fmaf(pp, v1.w, a1.w);
            a2.x = fmaf(qq, v2.x, a2.x); a2.y = fmaf(qq, v2.y, a2.y);
            a2.z = fmaf(qq, v2.z, a2.z); a2.w = fmaf(qq, v2.w, a2.w);
        }
    }
    float av = g_alpha + g_v[n];
    float wn = g_w[n];
    float cw = (float)N_EDGES * wn + g_r[n];
    float4 sv = ((const float4*)g_s )[lane];
    float4 tv = ((const float4*)g_t )[lane];
    float4 pv = ((const float4*)g_p1)[lane];
    float4 qv = ((const float4*)g_p2)[lane];
    float4 r;
    r.x = av*sv.x + tv.x + cw*pv.x + wn*qv.x + a1.x + a2.x;
    r.y = av*sv.y + tv.y + cw*pv.y + wn*qv.y + a1.y + a2.y;
    r.z = av*sv.z + tv.z + cw*pv.z + wn*qv.z + a1.z + a2.z;
    r.w = av*sv.w + tv.w + cw*pv.w + wn*qv.w + a1.w + a2.w;
    r.x = (r.x > 0.f) ? r.x : expm1f(r.x);
    r.y = (r.y > 0.f) ? r.y : expm1f(r.y);
    r.z = (r.z > 0.f) ? r.z : expm1f(r.z);
    r.w = (r.w > 0.f) ? r.w : expm1f(r.w);
    ((float4*)&out[(size_t)n * D_])[lane] = r;
}

// ---------------- launch ----------------
extern "C" void kernel_launch(void* const* d_in, const int* in_sizes, int n_in,
                              void* d_out, int out_size) {
    const float* x      = (const float*)d_in[0];
    const float* W      = (const float*)d_in[1];
    const float* W2     = (const float*)d_in[2];
    const float* W3     = (const float*)d_in[3];
    const float* bias   = (const float*)d_in[4];
    const float* q_ctx  = (const float*)d_in[5];
    const int*   hidx   = (const int*)d_in[6];
    const int* nodes = hidx;
    const int* edges = hidx + NNZ_IN;
    float* out = (float*)d_out;

    static cudaStream_t s_side = nullptr;
    static cudaEvent_t  ev_fork = nullptr, ev_join = nullptr;
    if (s_side == nullptr) {
        cudaStreamCreateWithFlags(&s_side, cudaStreamNonBlocking);
        cudaEventCreateWithFlags(&ev_fork, cudaEventDisableTiming);
        cudaEventCreateWithFlags(&ev_join, cudaEventDisableTiming);
    }

    cudaEventRecord(ev_fork, 0);
    cudaStreamWaitEvent(s_side, ev_fork, 0);

    k_zero_big<<<1024, 256, 0, s_side>>>();
    k_dedup<<<NNZ_IN / 256, 256, 0, s_side>>>(nodes, edges);
    k_scan2<<<2, 1024, 0, s_side>>>();
    k_fill<<<2 * NNZ_IN / 256, 256, 0, s_side>>>();
    cudaEventRecord(ev_join, s_side);

    k_zero_small<<<1, 256>>>();
    k_gemm_x<<<N_NODES / 32, 512>>>(x, W, W2, bias, q_ctx);

    cudaStreamWaitEvent(0, ev_join, 0);

    k_edge<<<N_EDGES / 8, 256>>>(W3);
    k_node2f<<<N2F_BLOCKS + N_NODES / 256, 256>>>();
    k_y2<<<N_EDGES / 8, 256>>>();
    k_final<<<N_NODES / 8, 256>>>(out);
}